// round 14
// baseline (speedup 1.0000x reference)
#include <cuda_runtime.h>

// Problem constants
#define BB      8
#define DIN     1024
#define TT      2048
#define KCB     8192
#define CD      8
#define NTOK    (BB*TT)            // 16384
#define NSPLIT  37
#define CPS     222                // codes per split (37*222 = 8214 >= 8192, padded)
#define KPAD    (NSPLIT*CPS)       // 8214
#define TOKBLK  1024               // tokens per search CTA (256 thr * 4 tok)

// Output buffer layout (float32, concatenated tuple)
#define OUT_OFF   0
#define LOSS_OFF  (BB*DIN*TT)                 // 16777216
#define IDX_OFF   (LOSS_OFF + 16)             // 16777232
#define ZE_OFF    (IDX_OFF + NTOK)            // 16793616

// Scratch (device globals — no allocation allowed)
__device__ float              g_enc[(size_t)NTOK*CD];  // normalized encodings, token-major
__device__ unsigned long long g_cbdup[(size_t)KPAD*9]; // per code: 8x {c,c} + {-c2/2,-c2/2}
__device__ unsigned long long g_wdup[(size_t)DIN*9];   // per out-row: 8x {w,w} + {b,b}
__device__ unsigned long long g_best[NTOK];            // atomicMax key: (mono(score)<<32)|(8191-idx)
__device__ unsigned long long g_zq2[CD][NTOK/2];       // z_q pair-packed: [k][tokpair]

// ---- packed f32x2 helpers ----
__device__ __forceinline__ unsigned long long pack2(float lo, float hi) {
    unsigned long long r;
    asm("mov.b64 %0, {%1,%2};" : "=l"(r) : "f"(lo), "f"(hi));
    return r;
}
__device__ __forceinline__ void unpack2(unsigned long long v, float& lo, float& hi) {
    asm("mov.b64 {%0,%1}, %2;" : "=f"(lo), "=f"(hi) : "l"(v));
}
__device__ __forceinline__ unsigned long long fma2(unsigned long long a, unsigned long long b,
                                                   unsigned long long c) {
    unsigned long long d;
    asm("fma.rn.f32x2 %0, %1, %2, %3;" : "=l"(d) : "l"(a), "l"(b), "l"(c));
    return d;
}
__device__ __forceinline__ unsigned long long add2(unsigned long long a, unsigned long long b) {
    unsigned long long d;
    asm("add.rn.f32x2 %0, %1, %2;" : "=l"(d) : "l"(a), "l"(b));
    return d;
}

// Monotonic key: unsigned compare on result == float compare on score.
// Low 32 bits: 8191 - idx  ->  score ties resolve to SMALLEST index (first-wins).
__device__ __forceinline__ unsigned long long mkkey(float s, int gidx) {
    unsigned u = __float_as_uint(s);
    unsigned m = u ^ ((unsigned)((int)u >> 31) | 0x80000000u);
    return ((unsigned long long)m << 32) | (unsigned)(KCB - 1 - gidx);
}

// ---------------------------------------------------------------------------
// K0: prep — normalize codebook into duplicated-pair table (padded with
//     sentinel codes that can never win), pack w_out/b_out, zero losses,
//     zero g_best (every call — graph replay safe).
// ---------------------------------------------------------------------------
__global__ void k_prep(const float* __restrict__ cb, const float* __restrict__ w_out,
                       const float* __restrict__ b_out, float* __restrict__ out) {
    int i = blockIdx.x * 256 + threadIdx.x;
    if (i < KCB) {
        float v[CD];
#pragma unroll
        for (int k = 0; k < CD; k++) v[k] = cb[(size_t)i * CD + k];
        float s = 0.0f;
#pragma unroll
        for (int k = 0; k < CD; k++) s += v[k] * v[k];
        float den = fmaxf(__fsqrt_rn(s), 1e-12f);
        float nv[CD];
#pragma unroll
        for (int k = 0; k < CD; k++) nv[k] = __fdiv_rn(v[k], den);
        float c2 = 0.0f;
#pragma unroll
        for (int k = 0; k < CD; k++) c2 += nv[k] * nv[k];
#pragma unroll
        for (int k = 0; k < CD; k++) g_cbdup[(size_t)i * 9 + k] = pack2(nv[k], nv[k]);
        float h = -0.5f * c2;
        g_cbdup[(size_t)i * 9 + 8] = pack2(h, h);
    } else if (i < KPAD) {
        // sentinel pad: score accumulates to -1e30, always loses to any real code
#pragma unroll
        for (int k = 0; k < CD; k++) g_cbdup[(size_t)i * 9 + k] = 0ull;
        g_cbdup[(size_t)i * 9 + 8] = pack2(-1e30f, -1e30f);
    } else if (i < KPAD + DIN) {
        int o = i - KPAD;
#pragma unroll
        for (int k = 0; k < CD; k++) {
            float w = w_out[(size_t)o * CD + k];
            g_wdup[(size_t)o * 9 + k] = pack2(w, w);
        }
        float bo = b_out[o];
        g_wdup[(size_t)o * 9 + 8] = pack2(bo, bo);
    } else if (i < KPAD + DIN + 16) {
        out[LOSS_OFF + (i - KPAD - DIN)] = 0.0f;
    } else if (i < KPAD + DIN + 16 + NTOK) {
        g_best[i - KPAD - DIN - 16] = 0ull;   // below any real key
    }
}

// ---------------------------------------------------------------------------
// K1 (fused): in-projection + bias + z_e store + L2-normalize into g_enc.
// grid (T/16, B) = 1024 CTAs, 256 threads.  CTA = 16 tokens x full D=1024.
// ---------------------------------------------------------------------------
__global__ void __launch_bounds__(256) k_inproj(const float* __restrict__ z,
                                                const float* __restrict__ w_in,
                                                const float* __restrict__ b_in,
                                                float* __restrict__ out) {
    __shared__ float sw[DIN * 8];                        // [d][o]  32 KB
    __shared__ unsigned long long sred[8][16][4];        // [warp][tok][pack] 4 KB

    int tid = threadIdx.x;
    for (int i = tid; i < DIN * 8; i += 256) {
        int o = i >> 10, d = i & 1023;
        sw[d * 8 + o] = w_in[i];
    }
    __syncthreads();

    int lane = tid & 31, warp = tid >> 5;
    int tokl = lane & 15;
    int segh = lane >> 4;                 // 0/1
    int seg = warp * 2 + segh;            // 0..15, 64 d each
    int b = blockIdx.y;
    int t = blockIdx.x * 16 + tokl;

    unsigned long long a01 = 0, a23 = 0, a45 = 0, a67 = 0;
    const float* zp = z + ((size_t)b * DIN + (size_t)seg * 64) * TT + t;
    const float* swp = &sw[seg * 64 * 8];
#pragma unroll 8
    for (int dd = 0; dd < 64; dd++) {
        float zv = zp[(size_t)dd * TT];
        unsigned long long zd = pack2(zv, zv);
        const ulonglong2* wp = reinterpret_cast<const ulonglong2*>(&swp[dd * 8]);
        ulonglong2 wA = wp[0], wB = wp[1];
        a01 = fma2(zd, wA.x, a01);
        a23 = fma2(zd, wA.y, a23);
        a45 = fma2(zd, wB.x, a45);
        a67 = fma2(zd, wB.y, a67);
    }
    a01 = add2(a01, __shfl_xor_sync(0xffffffffu, a01, 16));
    a23 = add2(a23, __shfl_xor_sync(0xffffffffu, a23, 16));
    a45 = add2(a45, __shfl_xor_sync(0xffffffffu, a45, 16));
    a67 = add2(a67, __shfl_xor_sync(0xffffffffu, a67, 16));
    if (segh == 0) {
        sred[warp][tokl][0] = a01; sred[warp][tokl][1] = a23;
        sred[warp][tokl][2] = a45; sred[warp][tokl][3] = a67;
    }
    __syncthreads();

    if (tid < 64) {
        int pk = tid & 3;        // channel pair {2pk, 2pk+1}
        int tk = tid >> 2;       // token slot 0..15
        unsigned long long s = sred[0][tk][pk];
#pragma unroll
        for (int w = 1; w < 8; w++) s = add2(s, sred[w][tk][pk]);
        float lo, hi;
        unpack2(s, lo, hi);
        lo += b_in[2 * pk];
        hi += b_in[2 * pk + 1];

        int tt = blockIdx.x * 16 + tk;
        out[ZE_OFF + ((size_t)b * 8 + 2 * pk) * TT + tt]     = lo;
        out[ZE_OFF + ((size_t)b * 8 + 2 * pk + 1) * TT + tt] = hi;

        float s2 = lo * lo + hi * hi;
        s2 += __shfl_xor_sync(0xffffffffu, s2, 1);
        s2 += __shfl_xor_sync(0xffffffffu, s2, 2);
        float den = fmaxf(__fsqrt_rn(s2), 1e-12f);
        int token = b * TT + tt;
        reinterpret_cast<unsigned long long*>(&g_enc[(size_t)token * 8])[pk] =
            pack2(__fdiv_rn(lo, den), __fdiv_rn(hi, den));
    }
}

// ---------------------------------------------------------------------------
// K3: nearest-code search.  grid(16 token-blocks, 37 code-splits) = 592 CTAs
// = exactly one full wave at 4 CTAs/SM.  256 thr, 4 tokens/thread, 222 codes.
// score = dot(enc_n, cb_n) - 0.5*c2  (argmax == reference argmin of dist)
// Result merged across splits via RED.MAX.U64 on a monotonic (score,idx) key.
// FMA-pipe bound at the fp32 floor (~70us); do not touch without a new pipe.
// ---------------------------------------------------------------------------
__global__ void __launch_bounds__(256, 4) k_search() {
    __shared__ unsigned long long s_cd[CPS][8];
    __shared__ unsigned long long s_c2[CPS];
    int tid = threadIdx.x;
    int cbase = blockIdx.y * CPS;

    for (int i = tid; i < CPS * 9; i += 256) {
        unsigned long long v = g_cbdup[(size_t)cbase * 9 + i];
        int j = i / 9, kk = i - j * 9;
        if (kk < 8) s_cd[j][kk] = v; else s_c2[j] = v;
    }

    int tok0 = blockIdx.x * TOKBLK + tid * 4;
    const float4* ep = reinterpret_cast<const float4*>(&g_enc[(size_t)tok0 * 8]);
    float4 p0 = ep[0], p1 = ep[1], p2 = ep[2], p3 = ep[3];
    float4 p4 = ep[4], p5 = ep[5], p6 = ep[6], p7 = ep[7];
    unsigned long long ea[8], eb[8];
    ea[0] = pack2(p0.x, p2.x); ea[1] = pack2(p0.y, p2.y);
    ea[2] = pack2(p0.z, p2.z); ea[3] = pack2(p0.w, p2.w);
    ea[4] = pack2(p1.x, p3.x); ea[5] = pack2(p1.y, p3.y);
    ea[6] = pack2(p1.z, p3.z); ea[7] = pack2(p1.w, p3.w);
    eb[0] = pack2(p4.x, p6.x); eb[1] = pack2(p4.y, p6.y);
    eb[2] = pack2(p4.z, p6.z); eb[3] = pack2(p4.w, p6.w);
    eb[4] = pack2(p5.x, p7.x); eb[5] = pack2(p5.y, p7.y);
    eb[6] = pack2(p5.z, p7.z); eb[7] = pack2(p5.w, p7.w);

    __syncthreads();

    float best0 = -3.4e38f, best1 = -3.4e38f, best2 = -3.4e38f, best3 = -3.4e38f;
    int bi0 = 0, bi1 = 0, bi2 = 0, bi3 = 0;

#pragma unroll 2
    for (int j = 0; j < CPS; j++) {
        unsigned long long c2p = s_c2[j];
        const ulonglong2* cp = reinterpret_cast<const ulonglong2*>(&s_cd[j][0]);
        ulonglong2 cA = cp[0], cB = cp[1], cC = cp[2], cD = cp[3];

        unsigned long long aA = fma2(ea[0], cA.x, c2p);
        unsigned long long aB = fma2(eb[0], cA.x, c2p);
        aA = fma2(ea[1], cA.y, aA);  aB = fma2(eb[1], cA.y, aB);
        aA = fma2(ea[2], cB.x, aA);  aB = fma2(eb[2], cB.x, aB);
        aA = fma2(ea[3], cB.y, aA);  aB = fma2(eb[3], cB.y, aB);
        aA = fma2(ea[4], cC.x, aA);  aB = fma2(eb[4], cC.x, aB);
        aA = fma2(ea[5], cC.y, aA);  aB = fma2(eb[5], cC.y, aB);
        aA = fma2(ea[6], cD.x, aA);  aB = fma2(eb[6], cD.x, aB);
        aA = fma2(ea[7], cD.y, aA);  aB = fma2(eb[7], cD.y, aB);

        float s0, s1, s2, s3;
        unpack2(aA, s0, s1);
        unpack2(aB, s2, s3);
        float n0 = fmaxf(best0, s0);
        float n1 = fmaxf(best1, s1);
        float n2 = fmaxf(best2, s2);
        float n3 = fmaxf(best3, s3);
        if (n0 != best0) bi0 = j;
        if (n1 != best1) bi1 = j;
        if (n2 != best2) bi2 = j;
        if (n3 != best3) bi3 = j;
        best0 = n0; best1 = n1; best2 = n2; best3 = n3;
    }

    atomicMax(&g_best[tok0 + 0], mkkey(best0, cbase + bi0));
    atomicMax(&g_best[tok0 + 1], mkkey(best1, cbase + bi1));
    atomicMax(&g_best[tok0 + 2], mkkey(best2, cbase + bi2));
    atomicMax(&g_best[tok0 + 3], mkkey(best3, cbase + bi3));
}

// ---------------------------------------------------------------------------
// K4: z_q staging.  Work-item = (token-pair, channel): 8192 x 8 = 65536 thr
// = 256 CTAs.  Warp = one channel k x 32 consecutive pairs -> all g_best /
// z_e / g_zq2 accesses coalesced; only the 2 codebook picks are scattered
// (codebook is L1/L2 resident).  k==0 warps also write the indices output.
// ---------------------------------------------------------------------------
__global__ void __launch_bounds__(256) k_zq(const float* __restrict__ cb,
                                            float* __restrict__ out) {
    int lane = threadIdx.x & 31;
    int k = threadIdx.x >> 5;                 // channel 0..7
    int tp = blockIdx.x * 32 + lane;          // pair index 0..8191
    int tok0 = tp * 2;
    int b = tok0 >> 11, t = tok0 & 2047;

    unsigned long long pk0 = g_best[tok0], pk1 = g_best[tok0 + 1];
    int i0 = KCB - 1 - (int)(unsigned)(pk0 & 0xffffffffu);
    int i1 = KCB - 1 - (int)(unsigned)(pk1 & 0xffffffffu);

    if (k == 0) {
        float2 iv;
        iv.x = (float)i0; iv.y = (float)i1;
        *reinterpret_cast<float2*>(&out[IDX_OFF + tok0]) = iv;
    }

    float q0 = cb[(size_t)i0 * CD + k];
    float q1 = cb[(size_t)i1 * CD + k];
    float2 ze = *reinterpret_cast<const float2*>(&out[ZE_OFF + ((size_t)b * 8 + k) * TT + t]);
    g_zq2[k][tp] = pack2(ze.x + (q0 - ze.x), ze.y + (q1 - ze.y));
}

// ---------------------------------------------------------------------------
// K5: out-projection.  grid(T/512, B, 64 o-splits of 16) = 2048 CTAs,
//     256 threads, 2 tokens/thread.  8 coalesced LDG.64 (pre-staged z_q),
//     16 o-rows with bias folded into fma chain init, STG.64 stores.
// ---------------------------------------------------------------------------
__global__ void __launch_bounds__(256, 6) k_outproj(float* __restrict__ out) {
    __shared__ unsigned long long s_w[16][8];
    __shared__ unsigned long long s_b[16];
    int tid = threadIdx.x;
    int ob = blockIdx.z * 16;
    if (tid < 16 * 9) {
        unsigned long long v = g_wdup[(size_t)ob * 9 + tid];
        int j = tid / 9, kk = tid - j * 9;
        if (kk < 8) s_w[j][kk] = v; else s_b[j] = v;
    }

    int b = blockIdx.y;
    int t0 = blockIdx.x * 512 + tid * 2;
    int tp = (b * TT + t0) >> 1;

    unsigned long long zq[8];
#pragma unroll
    for (int k = 0; k < 8; k++) zq[k] = g_zq2[k][tp];
    __syncthreads();

    float* obase = out + OUT_OFF + ((size_t)b * DIN + ob) * TT + t0;
#pragma unroll 4
    for (int o = 0; o < 16; o++) {
        const ulonglong2* wp = reinterpret_cast<const ulonglong2*>(&s_w[o][0]);
        ulonglong2 wA = wp[0], wB = wp[1], wC = wp[2], wD = wp[3];
        unsigned long long acc = fma2(zq[0], wA.x, s_b[o]);
        acc = fma2(zq[1], wA.y, acc);
        acc = fma2(zq[2], wB.x, acc);
        acc = fma2(zq[3], wB.y, acc);
        acc = fma2(zq[4], wC.x, acc);
        acc = fma2(zq[5], wC.y, acc);
        acc = fma2(zq[6], wD.x, acc);
        acc = fma2(zq[7], wD.y, acc);
        *reinterpret_cast<unsigned long long*>(&obase[(size_t)o * TT]) = acc;
    }
}

// ---------------------------------------------------------------------------
extern "C" void kernel_launch(void* const* d_in, const int* in_sizes, int n_in,
                              void* d_out, int out_size) {
    const float* z     = (const float*)d_in[0];
    const float* w_in  = (const float*)d_in[1];
    const float* b_in  = (const float*)d_in[2];
    const float* w_out = (const float*)d_in[3];
    const float* b_out = (const float*)d_in[4];
    const float* cb    = (const float*)d_in[5];
    float* out = (float*)d_out;

    k_prep<<<(KPAD + DIN + 16 + NTOK + 255) / 256, 256>>>(cb, w_out, b_out, out);

    dim3 g1(TT / 16, BB);              // (128, 8) = 1024 CTAs
    k_inproj<<<g1, 256>>>(z, w_in, b_in, out);

    dim3 g3(NTOK / TOKBLK, NSPLIT);    // (16, 37) = 592 CTAs = one full wave
    k_search<<<g3, 256>>>();

    k_zq<<<NTOK / 2 / 32, 256>>>(cb, out);   // 256 CTAs, (pair, k) work-items

    dim3 g5(TT / 512, BB, DIN / 16);   // (4, 8, 64) = 2048 CTAs
    k_outproj<<<g5, 256>>>(out);
}

// round 15
// speedup vs baseline: 1.0665x; 1.0665x over previous
#include <cuda_runtime.h>

// Problem constants
#define BB      8
#define DIN     1024
#define TT      2048
#define KCB     8192
#define CD      8
#define NTOK    (BB*TT)            // 16384
#define NSPLIT  37
#define CPS     222                // codes per split (37*222 = 8214 >= 8192, padded)
#define KPAD    (NSPLIT*CPS)       // 8214
#define TOKBLK  1024               // tokens per search CTA (256 thr * 4 tok)

// Output buffer layout (float32, concatenated tuple)
#define OUT_OFF   0
#define LOSS_OFF  (BB*DIN*TT)                 // 16777216
#define IDX_OFF   (LOSS_OFF + 16)             // 16777232
#define ZE_OFF    (IDX_OFF + NTOK)            // 16793616

// Scratch (device globals — no allocation allowed)
__device__ float              g_enc[(size_t)NTOK*CD];  // normalized encodings, token-major
__device__ unsigned long long g_cbdup[(size_t)KPAD*9]; // per code: 8x {c,c} + {-c2/2,-c2/2}
__device__ unsigned long long g_wdup[(size_t)DIN*9];   // per out-row: 8x {w,w} + {b,b}
__device__ unsigned long long g_best[NTOK];            // atomicMax key: (mono(score)<<32)|(8191-idx)
__device__ unsigned long long g_zq2[CD][NTOK/2];       // z_q pair-packed: [k][tokpair]

// ---- packed f32x2 helpers ----
__device__ __forceinline__ unsigned long long pack2(float lo, float hi) {
    unsigned long long r;
    asm("mov.b64 %0, {%1,%2};" : "=l"(r) : "f"(lo), "f"(hi));
    return r;
}
__device__ __forceinline__ void unpack2(unsigned long long v, float& lo, float& hi) {
    asm("mov.b64 {%0,%1}, %2;" : "=f"(lo), "=f"(hi) : "l"(v));
}
__device__ __forceinline__ unsigned long long fma2(unsigned long long a, unsigned long long b,
                                                   unsigned long long c) {
    unsigned long long d;
    asm("fma.rn.f32x2 %0, %1, %2, %3;" : "=l"(d) : "l"(a), "l"(b), "l"(c));
    return d;
}
__device__ __forceinline__ unsigned long long add2(unsigned long long a, unsigned long long b) {
    unsigned long long d;
    asm("add.rn.f32x2 %0, %1, %2;" : "=l"(d) : "l"(a), "l"(b));
    return d;
}

// Monotonic key: unsigned compare on result == float compare on score.
// Low 32 bits: 8191 - idx  ->  score ties resolve to SMALLEST index (first-wins).
__device__ __forceinline__ unsigned long long mkkey(float s, int gidx) {
    unsigned u = __float_as_uint(s);
    unsigned m = u ^ ((unsigned)((int)u >> 31) | 0x80000000u);
    return ((unsigned long long)m << 32) | (unsigned)(KCB - 1 - gidx);
}

// ---------------------------------------------------------------------------
// Prep work (formerly its own kernel): normalize codebook into the padded
// duplicated-pair table, pack w_out/b_out, zero losses, zero g_best.
// Executed by the first ~25.6K global threads of k_inproj — all consumers
// (search / zq / outproj) launch strictly after inproj completes.
// ---------------------------------------------------------------------------
__device__ __forceinline__ void do_prep_item(int i, const float* __restrict__ cb,
                                             const float* __restrict__ w_out,
                                             const float* __restrict__ b_out,
                                             float* __restrict__ out) {
    if (i < KCB) {
        float v[CD];
#pragma unroll
        for (int k = 0; k < CD; k++) v[k] = cb[(size_t)i * CD + k];
        float s = 0.0f;
#pragma unroll
        for (int k = 0; k < CD; k++) s += v[k] * v[k];
        float den = fmaxf(__fsqrt_rn(s), 1e-12f);
        float nv[CD];
#pragma unroll
        for (int k = 0; k < CD; k++) nv[k] = __fdiv_rn(v[k], den);
        float c2 = 0.0f;
#pragma unroll
        for (int k = 0; k < CD; k++) c2 += nv[k] * nv[k];
#pragma unroll
        for (int k = 0; k < CD; k++) g_cbdup[(size_t)i * 9 + k] = pack2(nv[k], nv[k]);
        float h = -0.5f * c2;
        g_cbdup[(size_t)i * 9 + 8] = pack2(h, h);
    } else if (i < KPAD) {
        // sentinel pad: score accumulates to -1e30, always loses to any real code
#pragma unroll
        for (int k = 0; k < CD; k++) g_cbdup[(size_t)i * 9 + k] = 0ull;
        g_cbdup[(size_t)i * 9 + 8] = pack2(-1e30f, -1e30f);
    } else if (i < KPAD + DIN) {
        int o = i - KPAD;
#pragma unroll
        for (int k = 0; k < CD; k++) {
            float w = w_out[(size_t)o * CD + k];
            g_wdup[(size_t)o * 9 + k] = pack2(w, w);
        }
        float bo = b_out[o];
        g_wdup[(size_t)o * 9 + 8] = pack2(bo, bo);
    } else if (i < KPAD + DIN + 16) {
        out[LOSS_OFF + (i - KPAD - DIN)] = 0.0f;
    } else if (i < KPAD + DIN + 16 + NTOK) {
        g_best[i - KPAD - DIN - 16] = 0ull;   // below any real key
    }
}

// ---------------------------------------------------------------------------
// K1 (fused): prep prologue + in-projection + bias + z_e store + L2-normalize.
// grid (T/16, B) = 1024 CTAs, 256 threads.  CTA = 16 tokens x full D=1024.
// ---------------------------------------------------------------------------
__global__ void __launch_bounds__(256) k_inproj(const float* __restrict__ z,
                                                const float* __restrict__ w_in,
                                                const float* __restrict__ b_in,
                                                const float* __restrict__ cb,
                                                const float* __restrict__ w_out,
                                                const float* __restrict__ b_out,
                                                float* __restrict__ out) {
    __shared__ float sw[DIN * 8];                        // [d][o]  32 KB
    __shared__ unsigned long long sred[8][16][4];        // [warp][tok][pack] 4 KB

    int tid = threadIdx.x;

    // --- prep prologue: first 25638 global threads each handle one item ---
    {
        int bid = blockIdx.y * gridDim.x + blockIdx.x;   // 0..1023
        int gid = bid * 256 + tid;
        if (gid < KPAD + DIN + 16 + NTOK)
            do_prep_item(gid, cb, w_out, b_out, out);
    }

    for (int i = tid; i < DIN * 8; i += 256) {
        int o = i >> 10, d = i & 1023;
        sw[d * 8 + o] = w_in[i];
    }
    __syncthreads();

    int lane = tid & 31, warp = tid >> 5;
    int tokl = lane & 15;
    int segh = lane >> 4;                 // 0/1
    int seg = warp * 2 + segh;            // 0..15, 64 d each
    int b = blockIdx.y;
    int t = blockIdx.x * 16 + tokl;

    unsigned long long a01 = 0, a23 = 0, a45 = 0, a67 = 0;
    const float* zp = z + ((size_t)b * DIN + (size_t)seg * 64) * TT + t;
    const float* swp = &sw[seg * 64 * 8];
#pragma unroll 8
    for (int dd = 0; dd < 64; dd++) {
        float zv = zp[(size_t)dd * TT];
        unsigned long long zd = pack2(zv, zv);
        const ulonglong2* wp = reinterpret_cast<const ulonglong2*>(&swp[dd * 8]);
        ulonglong2 wA = wp[0], wB = wp[1];
        a01 = fma2(zd, wA.x, a01);
        a23 = fma2(zd, wA.y, a23);
        a45 = fma2(zd, wB.x, a45);
        a67 = fma2(zd, wB.y, a67);
    }
    a01 = add2(a01, __shfl_xor_sync(0xffffffffu, a01, 16));
    a23 = add2(a23, __shfl_xor_sync(0xffffffffu, a23, 16));
    a45 = add2(a45, __shfl_xor_sync(0xffffffffu, a45, 16));
    a67 = add2(a67, __shfl_xor_sync(0xffffffffu, a67, 16));
    if (segh == 0) {
        sred[warp][tokl][0] = a01; sred[warp][tokl][1] = a23;
        sred[warp][tokl][2] = a45; sred[warp][tokl][3] = a67;
    }
    __syncthreads();

    if (tid < 64) {
        int pk = tid & 3;        // channel pair {2pk, 2pk+1}
        int tk = tid >> 2;       // token slot 0..15
        unsigned long long s = sred[0][tk][pk];
#pragma unroll
        for (int w = 1; w < 8; w++) s = add2(s, sred[w][tk][pk]);
        float lo, hi;
        unpack2(s, lo, hi);
        lo += b_in[2 * pk];
        hi += b_in[2 * pk + 1];

        int tt = blockIdx.x * 16 + tk;
        out[ZE_OFF + ((size_t)b * 8 + 2 * pk) * TT + tt]     = lo;
        out[ZE_OFF + ((size_t)b * 8 + 2 * pk + 1) * TT + tt] = hi;

        float s2 = lo * lo + hi * hi;
        s2 += __shfl_xor_sync(0xffffffffu, s2, 1);
        s2 += __shfl_xor_sync(0xffffffffu, s2, 2);
        float den = fmaxf(__fsqrt_rn(s2), 1e-12f);
        int token = b * TT + tt;
        reinterpret_cast<unsigned long long*>(&g_enc[(size_t)token * 8])[pk] =
            pack2(__fdiv_rn(lo, den), __fdiv_rn(hi, den));
    }
}

// ---------------------------------------------------------------------------
// K3: nearest-code search.  grid(16 token-blocks, 37 code-splits) = 592 CTAs
// = exactly one full wave at 4 CTAs/SM.  256 thr, 4 tokens/thread, 222 codes.
// score = dot(enc_n, cb_n) - 0.5*c2  (argmax == reference argmin of dist)
// Best-update uses FMNMX + bit-pattern ISETP (all alu-pipe) so the fma pipe
// carries ONLY the 16 fma2/code.  Bit-equal max => no index change => first-
// index-wins tie rule preserved.
// Result merged across splits via RED.MAX.U64 on a monotonic (score,idx) key.
// ---------------------------------------------------------------------------
__global__ void __launch_bounds__(256, 4) k_search() {
    __shared__ unsigned long long s_cd[CPS][8];
    __shared__ unsigned long long s_c2[CPS];
    int tid = threadIdx.x;
    int cbase = blockIdx.y * CPS;

    for (int i = tid; i < CPS * 9; i += 256) {
        unsigned long long v = g_cbdup[(size_t)cbase * 9 + i];
        int j = i / 9, kk = i - j * 9;
        if (kk < 8) s_cd[j][kk] = v; else s_c2[j] = v;
    }

    int tok0 = blockIdx.x * TOKBLK + tid * 4;
    const float4* ep = reinterpret_cast<const float4*>(&g_enc[(size_t)tok0 * 8]);
    float4 p0 = ep[0], p1 = ep[1], p2 = ep[2], p3 = ep[3];
    float4 p4 = ep[4], p5 = ep[5], p6 = ep[6], p7 = ep[7];
    unsigned long long ea[8], eb[8];
    ea[0] = pack2(p0.x, p2.x); ea[1] = pack2(p0.y, p2.y);
    ea[2] = pack2(p0.z, p2.z); ea[3] = pack2(p0.w, p2.w);
    ea[4] = pack2(p1.x, p3.x); ea[5] = pack2(p1.y, p3.y);
    ea[6] = pack2(p1.z, p3.z); ea[7] = pack2(p1.w, p3.w);
    eb[0] = pack2(p4.x, p6.x); eb[1] = pack2(p4.y, p6.y);
    eb[2] = pack2(p4.z, p6.z); eb[3] = pack2(p4.w, p6.w);
    eb[4] = pack2(p5.x, p7.x); eb[5] = pack2(p5.y, p7.y);
    eb[6] = pack2(p5.z, p7.z); eb[7] = pack2(p5.w, p7.w);

    __syncthreads();

    float best0 = -3.4e38f, best1 = -3.4e38f, best2 = -3.4e38f, best3 = -3.4e38f;
    int bi0 = 0, bi1 = 0, bi2 = 0, bi3 = 0;

#pragma unroll 2
    for (int j = 0; j < CPS; j++) {
        unsigned long long c2p = s_c2[j];
        const ulonglong2* cp = reinterpret_cast<const ulonglong2*>(&s_cd[j][0]);
        ulonglong2 cA = cp[0], cB = cp[1], cC = cp[2], cD = cp[3];

        unsigned long long aA = fma2(ea[0], cA.x, c2p);
        unsigned long long aB = fma2(eb[0], cA.x, c2p);
        aA = fma2(ea[1], cA.y, aA);  aB = fma2(eb[1], cA.y, aB);
        aA = fma2(ea[2], cB.x, aA);  aB = fma2(eb[2], cB.x, aB);
        aA = fma2(ea[3], cB.y, aA);  aB = fma2(eb[3], cB.y, aB);
        aA = fma2(ea[4], cC.x, aA);  aB = fma2(eb[4], cC.x, aB);
        aA = fma2(ea[5], cC.y, aA);  aB = fma2(eb[5], cC.y, aB);
        aA = fma2(ea[6], cD.x, aA);  aB = fma2(eb[6], cD.x, aB);
        aA = fma2(ea[7], cD.y, aA);  aB = fma2(eb[7], cD.y, aB);

        float s0, s1, s2, s3;
        unpack2(aA, s0, s1);
        unpack2(aB, s2, s3);
        float n0 = fmaxf(best0, s0);
        float n1 = fmaxf(best1, s1);
        float n2 = fmaxf(best2, s2);
        float n3 = fmaxf(best3, s3);
        if (__float_as_uint(n0) != __float_as_uint(best0)) bi0 = j;
        if (__float_as_uint(n1) != __float_as_uint(best1)) bi1 = j;
        if (__float_as_uint(n2) != __float_as_uint(best2)) bi2 = j;
        if (__float_as_uint(n3) != __float_as_uint(best3)) bi3 = j;
        best0 = n0; best1 = n1; best2 = n2; best3 = n3;
    }

    atomicMax(&g_best[tok0 + 0], mkkey(best0, cbase + bi0));
    atomicMax(&g_best[tok0 + 1], mkkey(best1, cbase + bi1));
    atomicMax(&g_best[tok0 + 2], mkkey(best2, cbase + bi2));
    atomicMax(&g_best[tok0 + 3], mkkey(best3, cbase + bi3));
}

// ---------------------------------------------------------------------------
// K4: z_q staging.  Work-item = (token-pair, channel): 8192 x 8 = 65536 thr
// = 256 CTAs.  Warp = one channel k x 32 consecutive pairs -> all g_best /
// z_e / g_zq2 accesses coalesced; only the 2 codebook picks are scattered
// (codebook is L1/L2 resident).  k==0 warps also write the indices output.
// ---------------------------------------------------------------------------
__global__ void __launch_bounds__(256) k_zq(const float* __restrict__ cb,
                                            float* __restrict__ out) {
    int lane = threadIdx.x & 31;
    int k = threadIdx.x >> 5;                 // channel 0..7
    int tp = blockIdx.x * 32 + lane;          // pair index 0..8191
    int tok0 = tp * 2;
    int b = tok0 >> 11, t = tok0 & 2047;

    unsigned long long pk0 = g_best[tok0], pk1 = g_best[tok0 + 1];
    int i0 = KCB - 1 - (int)(unsigned)(pk0 & 0xffffffffu);
    int i1 = KCB - 1 - (int)(unsigned)(pk1 & 0xffffffffu);

    if (k == 0) {
        float2 iv;
        iv.x = (float)i0; iv.y = (float)i1;
        *reinterpret_cast<float2*>(&out[IDX_OFF + tok0]) = iv;
    }

    float q0 = cb[(size_t)i0 * CD + k];
    float q1 = cb[(size_t)i1 * CD + k];
    float2 ze = *reinterpret_cast<const float2*>(&out[ZE_OFF + ((size_t)b * 8 + k) * TT + t]);
    g_zq2[k][tp] = pack2(ze.x + (q0 - ze.x), ze.y + (q1 - ze.y));
}

// ---------------------------------------------------------------------------
// K5: out-projection.  grid(T/512, B, 64 o-splits of 16) = 2048 CTAs,
//     256 threads, 2 tokens/thread.  8 coalesced LDG.64 (pre-staged z_q),
//     16 o-rows with bias folded into fma chain init, STG.64 stores.
// ---------------------------------------------------------------------------
__global__ void __launch_bounds__(256, 6) k_outproj(float* __restrict__ out) {
    __shared__ unsigned long long s_w[16][8];
    __shared__ unsigned long long s_b[16];
    int tid = threadIdx.x;
    int ob = blockIdx.z * 16;
    if (tid < 16 * 9) {
        unsigned long long v = g_wdup[(size_t)ob * 9 + tid];
        int j = tid / 9, kk = tid - j * 9;
        if (kk < 8) s_w[j][kk] = v; else s_b[j] = v;
    }

    int b = blockIdx.y;
    int t0 = blockIdx.x * 512 + tid * 2;
    int tp = (b * TT + t0) >> 1;

    unsigned long long zq[8];
#pragma unroll
    for (int k = 0; k < 8; k++) zq[k] = g_zq2[k][tp];
    __syncthreads();

    float* obase = out + OUT_OFF + ((size_t)b * DIN + ob) * TT + t0;
#pragma unroll 4
    for (int o = 0; o < 16; o++) {
        const ulonglong2* wp = reinterpret_cast<const ulonglong2*>(&s_w[o][0]);
        ulonglong2 wA = wp[0], wB = wp[1], wC = wp[2], wD = wp[3];
        unsigned long long acc = fma2(zq[0], wA.x, s_b[o]);
        acc = fma2(zq[1], wA.y, acc);
        acc = fma2(zq[2], wB.x, acc);
        acc = fma2(zq[3], wB.y, acc);
        acc = fma2(zq[4], wC.x, acc);
        acc = fma2(zq[5], wC.y, acc);
        acc = fma2(zq[6], wD.x, acc);
        acc = fma2(zq[7], wD.y, acc);
        *reinterpret_cast<unsigned long long*>(&obase[(size_t)o * TT]) = acc;
    }
}

// ---------------------------------------------------------------------------
extern "C" void kernel_launch(void* const* d_in, const int* in_sizes, int n_in,
                              void* d_out, int out_size) {
    const float* z     = (const float*)d_in[0];
    const float* w_in  = (const float*)d_in[1];
    const float* b_in  = (const float*)d_in[2];
    const float* w_out = (const float*)d_in[3];
    const float* b_out = (const float*)d_in[4];
    const float* cb    = (const float*)d_in[5];
    float* out = (float*)d_out;

    dim3 g1(TT / 16, BB);              // (128, 8) = 1024 CTAs, prep folded in
    k_inproj<<<g1, 256>>>(z, w_in, b_in, cb, w_out, b_out, out);

    dim3 g3(NTOK / TOKBLK, NSPLIT);    // (16, 37) = 592 CTAs = one full wave
    k_search<<<g3, 256>>>();

    k_zq<<<NTOK / 2 / 32, 256>>>(cb, out);   // 256 CTAs, (pair, k) work-items

    dim3 g5(TT / 512, BB, DIN / 16);   // (4, 8, 64) = 2048 CTAs
    k_outproj<<<g5, 256>>>(out);
}

// round 16
// speedup vs baseline: 1.1021x; 1.0334x over previous
#include <cuda_runtime.h>

// Problem constants
#define BB      8
#define DIN     1024
#define TT      2048
#define KCB     8192
#define CD      8
#define NTOK    (BB*TT)            // 16384
#define NSPLIT  37
#define CPS     222                // codes per split (37*222 = 8214 >= 8192, padded)
#define KPAD    (NSPLIT*CPS)       // 8214
#define TOKBLK  1024               // tokens per search CTA (256 thr * 4 tok)

// Output buffer layout (float32, concatenated tuple)
#define OUT_OFF   0
#define LOSS_OFF  (BB*DIN*TT)                 // 16777216
#define IDX_OFF   (LOSS_OFF + 16)             // 16777232
#define ZE_OFF    (IDX_OFF + NTOK)            // 16793616

// Scratch (device globals — no allocation allowed)
__device__ float              g_enc[(size_t)NTOK*CD];  // normalized encodings, token-major
__device__ unsigned long long g_cbdup[(size_t)KPAD*9]; // per code: 8x {c,c} + {-c2/2,-c2/2}
__device__ unsigned long long g_wdup[(size_t)DIN*9];   // per out-row: 8x {w,w} + {b,b}
__device__ unsigned long long g_best[NTOK];            // atomicMax key: (mono(score)<<32)|(8191-idx)
__device__ unsigned long long g_zq2[CD][NTOK/2];       // z_q pair-packed: [k][tokpair]

// ---- packed f32x2 helpers ----
__device__ __forceinline__ unsigned long long pack2(float lo, float hi) {
    unsigned long long r;
    asm("mov.b64 %0, {%1,%2};" : "=l"(r) : "f"(lo), "f"(hi));
    return r;
}
__device__ __forceinline__ void unpack2(unsigned long long v, float& lo, float& hi) {
    asm("mov.b64 {%0,%1}, %2;" : "=f"(lo), "=f"(hi) : "l"(v));
}
__device__ __forceinline__ unsigned long long fma2(unsigned long long a, unsigned long long b,
                                                   unsigned long long c) {
    unsigned long long d;
    asm("fma.rn.f32x2 %0, %1, %2, %3;" : "=l"(d) : "l"(a), "l"(b), "l"(c));
    return d;
}
__device__ __forceinline__ unsigned long long add2(unsigned long long a, unsigned long long b) {
    unsigned long long d;
    asm("add.rn.f32x2 %0, %1, %2;" : "=l"(d) : "l"(a), "l"(b));
    return d;
}

// Monotonic key: unsigned compare on result == float compare on score.
// Low 32 bits: 8191 - idx  ->  score ties resolve to SMALLEST index (first-wins).
__device__ __forceinline__ unsigned long long mkkey(float s, int gidx) {
    unsigned u = __float_as_uint(s);
    unsigned m = u ^ ((unsigned)((int)u >> 31) | 0x80000000u);
    return ((unsigned long long)m << 32) | (unsigned)(KCB - 1 - gidx);
}

// ---------------------------------------------------------------------------
// Prep work (folded into k_inproj prologue): normalize codebook into the
// padded duplicated-pair table, pack w_out/b_out, zero losses, zero g_best.
// ---------------------------------------------------------------------------
__device__ __forceinline__ void do_prep_item(int i, const float* __restrict__ cb,
                                             const float* __restrict__ w_out,
                                             const float* __restrict__ b_out,
                                             float* __restrict__ out) {
    if (i < KCB) {
        float v[CD];
#pragma unroll
        for (int k = 0; k < CD; k++) v[k] = cb[(size_t)i * CD + k];
        float s = 0.0f;
#pragma unroll
        for (int k = 0; k < CD; k++) s += v[k] * v[k];
        float den = fmaxf(__fsqrt_rn(s), 1e-12f);
        float nv[CD];
#pragma unroll
        for (int k = 0; k < CD; k++) nv[k] = __fdiv_rn(v[k], den);
        float c2 = 0.0f;
#pragma unroll
        for (int k = 0; k < CD; k++) c2 += nv[k] * nv[k];
#pragma unroll
        for (int k = 0; k < CD; k++) g_cbdup[(size_t)i * 9 + k] = pack2(nv[k], nv[k]);
        float h = -0.5f * c2;
        g_cbdup[(size_t)i * 9 + 8] = pack2(h, h);
    } else if (i < KPAD) {
        // sentinel pad: score accumulates to -1e30, always loses to any real code
#pragma unroll
        for (int k = 0; k < CD; k++) g_cbdup[(size_t)i * 9 + k] = 0ull;
        g_cbdup[(size_t)i * 9 + 8] = pack2(-1e30f, -1e30f);
    } else if (i < KPAD + DIN) {
        int o = i - KPAD;
#pragma unroll
        for (int k = 0; k < CD; k++) {
            float w = w_out[(size_t)o * CD + k];
            g_wdup[(size_t)o * 9 + k] = pack2(w, w);
        }
        float bo = b_out[o];
        g_wdup[(size_t)o * 9 + 8] = pack2(bo, bo);
    } else if (i < KPAD + DIN + 16) {
        out[LOSS_OFF + (i - KPAD - DIN)] = 0.0f;
    } else if (i < KPAD + DIN + 16 + NTOK) {
        g_best[i - KPAD - DIN - 16] = 0ull;   // below any real key
    }
}

// ---------------------------------------------------------------------------
// K1 (fused): prep prologue + in-projection + bias + z_e store + L2-normalize.
// grid (T/16, B) = 1024 CTAs, 256 threads.  CTA = 16 tokens x full D=1024.
// ---------------------------------------------------------------------------
__global__ void __launch_bounds__(256) k_inproj(const float* __restrict__ z,
                                                const float* __restrict__ w_in,
                                                const float* __restrict__ b_in,
                                                const float* __restrict__ cb,
                                                const float* __restrict__ w_out,
                                                const float* __restrict__ b_out,
                                                float* __restrict__ out) {
    __shared__ float sw[DIN * 8];                        // [d][o]  32 KB
    __shared__ unsigned long long sred[8][16][4];        // [warp][tok][pack] 4 KB

    int tid = threadIdx.x;

    // --- prep prologue: first 25638 global threads each handle one item ---
    {
        int bid = blockIdx.y * gridDim.x + blockIdx.x;   // 0..1023
        int gid = bid * 256 + tid;
        if (gid < KPAD + DIN + 16 + NTOK)
            do_prep_item(gid, cb, w_out, b_out, out);
    }

    for (int i = tid; i < DIN * 8; i += 256) {
        int o = i >> 10, d = i & 1023;
        sw[d * 8 + o] = w_in[i];
    }
    __syncthreads();

    int lane = tid & 31, warp = tid >> 5;
    int tokl = lane & 15;
    int segh = lane >> 4;                 // 0/1
    int seg = warp * 2 + segh;            // 0..15, 64 d each
    int b = blockIdx.y;
    int t = blockIdx.x * 16 + tokl;

    unsigned long long a01 = 0, a23 = 0, a45 = 0, a67 = 0;
    const float* zp = z + ((size_t)b * DIN + (size_t)seg * 64) * TT + t;
    const float* swp = &sw[seg * 64 * 8];
#pragma unroll 8
    for (int dd = 0; dd < 64; dd++) {
        float zv = zp[(size_t)dd * TT];
        unsigned long long zd = pack2(zv, zv);
        const ulonglong2* wp = reinterpret_cast<const ulonglong2*>(&swp[dd * 8]);
        ulonglong2 wA = wp[0], wB = wp[1];
        a01 = fma2(zd, wA.x, a01);
        a23 = fma2(zd, wA.y, a23);
        a45 = fma2(zd, wB.x, a45);
        a67 = fma2(zd, wB.y, a67);
    }
    a01 = add2(a01, __shfl_xor_sync(0xffffffffu, a01, 16));
    a23 = add2(a23, __shfl_xor_sync(0xffffffffu, a23, 16));
    a45 = add2(a45, __shfl_xor_sync(0xffffffffu, a45, 16));
    a67 = add2(a67, __shfl_xor_sync(0xffffffffu, a67, 16));
    if (segh == 0) {
        sred[warp][tokl][0] = a01; sred[warp][tokl][1] = a23;
        sred[warp][tokl][2] = a45; sred[warp][tokl][3] = a67;
    }
    __syncthreads();

    if (tid < 64) {
        int pk = tid & 3;        // channel pair {2pk, 2pk+1}
        int tk = tid >> 2;       // token slot 0..15
        unsigned long long s = sred[0][tk][pk];
#pragma unroll
        for (int w = 1; w < 8; w++) s = add2(s, sred[w][tk][pk]);
        float lo, hi;
        unpack2(s, lo, hi);
        lo += b_in[2 * pk];
        hi += b_in[2 * pk + 1];

        int tt = blockIdx.x * 16 + tk;
        out[ZE_OFF + ((size_t)b * 8 + 2 * pk) * TT + tt]     = lo;
        out[ZE_OFF + ((size_t)b * 8 + 2 * pk + 1) * TT + tt] = hi;

        float s2 = lo * lo + hi * hi;
        s2 += __shfl_xor_sync(0xffffffffu, s2, 1);
        s2 += __shfl_xor_sync(0xffffffffu, s2, 2);
        float den = fmaxf(__fsqrt_rn(s2), 1e-12f);
        int token = b * TT + tt;
        reinterpret_cast<unsigned long long*>(&g_enc[(size_t)token * 8])[pk] =
            pack2(__fdiv_rn(lo, den), __fdiv_rn(hi, den));
    }
}

// ---------------------------------------------------------------------------
// K3: nearest-code search.  grid(16 token-blocks, 37 code-splits) = 592 CTAs
// = exactly one full wave at 4 CTAs/SM.  256 thr, 4 tokens/thread, 222 codes.
// score = dot(enc_n, cb_n) - 0.5*c2  (argmax == reference argmin of dist)
// Best-update uses FMNMX + bit-pattern ISETP (all alu-pipe); the fma pipe
// carries only the 16 fma2/code.  FMA-pipe bound at rt4 floor (~64us).
// Result merged across splits via RED.MAX.U64 on a monotonic (score,idx) key.
// ---------------------------------------------------------------------------
__global__ void __launch_bounds__(256, 4) k_search() {
    __shared__ unsigned long long s_cd[CPS][8];
    __shared__ unsigned long long s_c2[CPS];
    int tid = threadIdx.x;
    int cbase = blockIdx.y * CPS;

    for (int i = tid; i < CPS * 9; i += 256) {
        unsigned long long v = g_cbdup[(size_t)cbase * 9 + i];
        int j = i / 9, kk = i - j * 9;
        if (kk < 8) s_cd[j][kk] = v; else s_c2[j] = v;
    }

    int tok0 = blockIdx.x * TOKBLK + tid * 4;
    const float4* ep = reinterpret_cast<const float4*>(&g_enc[(size_t)tok0 * 8]);
    float4 p0 = ep[0], p1 = ep[1], p2 = ep[2], p3 = ep[3];
    float4 p4 = ep[4], p5 = ep[5], p6 = ep[6], p7 = ep[7];
    unsigned long long ea[8], eb[8];
    ea[0] = pack2(p0.x, p2.x); ea[1] = pack2(p0.y, p2.y);
    ea[2] = pack2(p0.z, p2.z); ea[3] = pack2(p0.w, p2.w);
    ea[4] = pack2(p1.x, p3.x); ea[5] = pack2(p1.y, p3.y);
    ea[6] = pack2(p1.z, p3.z); ea[7] = pack2(p1.w, p3.w);
    eb[0] = pack2(p4.x, p6.x); eb[1] = pack2(p4.y, p6.y);
    eb[2] = pack2(p4.z, p6.z); eb[3] = pack2(p4.w, p6.w);
    eb[4] = pack2(p5.x, p7.x); eb[5] = pack2(p5.y, p7.y);
    eb[6] = pack2(p5.z, p7.z); eb[7] = pack2(p5.w, p7.w);

    __syncthreads();

    float best0 = -3.4e38f, best1 = -3.4e38f, best2 = -3.4e38f, best3 = -3.4e38f;
    int bi0 = 0, bi1 = 0, bi2 = 0, bi3 = 0;

#pragma unroll 2
    for (int j = 0; j < CPS; j++) {
        unsigned long long c2p = s_c2[j];
        const ulonglong2* cp = reinterpret_cast<const ulonglong2*>(&s_cd[j][0]);
        ulonglong2 cA = cp[0], cB = cp[1], cC = cp[2], cD = cp[3];

        unsigned long long aA = fma2(ea[0], cA.x, c2p);
        unsigned long long aB = fma2(eb[0], cA.x, c2p);
        aA = fma2(ea[1], cA.y, aA);  aB = fma2(eb[1], cA.y, aB);
        aA = fma2(ea[2], cB.x, aA);  aB = fma2(eb[2], cB.x, aB);
        aA = fma2(ea[3], cB.y, aA);  aB = fma2(eb[3], cB.y, aB);
        aA = fma2(ea[4], cC.x, aA);  aB = fma2(eb[4], cC.x, aB);
        aA = fma2(ea[5], cC.y, aA);  aB = fma2(eb[5], cC.y, aB);
        aA = fma2(ea[6], cD.x, aA);  aB = fma2(eb[6], cD.x, aB);
        aA = fma2(ea[7], cD.y, aA);  aB = fma2(eb[7], cD.y, aB);

        float s0, s1, s2, s3;
        unpack2(aA, s0, s1);
        unpack2(aB, s2, s3);
        float n0 = fmaxf(best0, s0);
        float n1 = fmaxf(best1, s1);
        float n2 = fmaxf(best2, s2);
        float n3 = fmaxf(best3, s3);
        if (__float_as_uint(n0) != __float_as_uint(best0)) bi0 = j;
        if (__float_as_uint(n1) != __float_as_uint(best1)) bi1 = j;
        if (__float_as_uint(n2) != __float_as_uint(best2)) bi2 = j;
        if (__float_as_uint(n3) != __float_as_uint(best3)) bi3 = j;
        best0 = n0; best1 = n1; best2 = n2; best3 = n3;
    }

    atomicMax(&g_best[tok0 + 0], mkkey(best0, cbase + bi0));
    atomicMax(&g_best[tok0 + 1], mkkey(best1, cbase + bi1));
    atomicMax(&g_best[tok0 + 2], mkkey(best2, cbase + bi2));
    atomicMax(&g_best[tok0 + 3], mkkey(best3, cbase + bi3));
}

// ---------------------------------------------------------------------------
// K4: z_q staging.  Work-item = (token-pair, channel): 8192 x 8 = 65536 thr
// = 256 CTAs.  Warp = one channel k x 32 consecutive pairs -> all g_best /
// z_e / g_zq2 accesses coalesced; only the 2 codebook picks are scattered
// (codebook is L1/L2 resident).  k==0 warps also write the indices output.
// ---------------------------------------------------------------------------
__global__ void __launch_bounds__(256) k_zq(const float* __restrict__ cb,
                                            float* __restrict__ out) {
    int lane = threadIdx.x & 31;
    int k = threadIdx.x >> 5;                 // channel 0..7
    int tp = blockIdx.x * 32 + lane;          // pair index 0..8191
    int tok0 = tp * 2;
    int b = tok0 >> 11, t = tok0 & 2047;

    unsigned long long pk0 = g_best[tok0], pk1 = g_best[tok0 + 1];
    int i0 = KCB - 1 - (int)(unsigned)(pk0 & 0xffffffffu);
    int i1 = KCB - 1 - (int)(unsigned)(pk1 & 0xffffffffu);

    if (k == 0) {
        float2 iv;
        iv.x = (float)i0; iv.y = (float)i1;
        *reinterpret_cast<float2*>(&out[IDX_OFF + tok0]) = iv;
    }

    float q0 = cb[(size_t)i0 * CD + k];
    float q1 = cb[(size_t)i1 * CD + k];
    float2 ze = *reinterpret_cast<const float2*>(&out[ZE_OFF + ((size_t)b * 8 + k) * TT + t]);
    g_zq2[k][tp] = pack2(ze.x + (q0 - ze.x), ze.y + (q1 - ze.y));
}

// ---------------------------------------------------------------------------
// K5: out-projection.  grid(T/1024, B, 64 o-splits of 16) = 1024 CTAs,
//     256 threads, 4 tokens/thread (two f32x2 pairs).  LDG.128 zq loads,
//     16 o-rows with bias folded into fma chain init, STG.128 stores.
// ---------------------------------------------------------------------------
__global__ void __launch_bounds__(256, 4) k_outproj(float* __restrict__ out) {
    __shared__ unsigned long long s_w[16][8];
    __shared__ unsigned long long s_b[16];
    int tid = threadIdx.x;
    int ob = blockIdx.z * 16;
    if (tid < 16 * 9) {
        unsigned long long v = g_wdup[(size_t)ob * 9 + tid];
        int j = tid / 9, kk = tid - j * 9;
        if (kk < 8) s_w[j][kk] = v; else s_b[j] = v;
    }

    int b = blockIdx.y;
    int t0 = blockIdx.x * 1024 + tid * 4;
    int tp = (b * TT + t0) >> 1;          // even: two consecutive pairs

    ulonglong2 zq[8];                      // .x = pair A (tok0,1), .y = pair B (tok2,3)
#pragma unroll
    for (int k = 0; k < 8; k++)
        zq[k] = *reinterpret_cast<const ulonglong2*>(&g_zq2[k][tp]);
    __syncthreads();

    float* obase = out + OUT_OFF + ((size_t)b * DIN + ob) * TT + t0;
#pragma unroll 2
    for (int o = 0; o < 16; o++) {
        const ulonglong2* wp = reinterpret_cast<const ulonglong2*>(&s_w[o][0]);
        ulonglong2 wA = wp[0], wB = wp[1], wC = wp[2], wD = wp[3];
        unsigned long long bias = s_b[o];
        unsigned long long aA = fma2(zq[0].x, wA.x, bias);
        unsigned long long aB = fma2(zq[0].y, wA.x, bias);
        aA = fma2(zq[1].x, wA.y, aA);  aB = fma2(zq[1].y, wA.y, aB);
        aA = fma2(zq[2].x, wB.x, aA);  aB = fma2(zq[2].y, wB.x, aB);
        aA = fma2(zq[3].x, wB.y, aA);  aB = fma2(zq[3].y, wB.y, aB);
        aA = fma2(zq[4].x, wC.x, aA);  aB = fma2(zq[4].y, wC.x, aB);
        aA = fma2(zq[5].x, wC.y, aA);  aB = fma2(zq[5].y, wC.y, aB);
        aA = fma2(zq[6].x, wD.x, aA);  aB = fma2(zq[6].y, wD.x, aB);
        aA = fma2(zq[7].x, wD.y, aA);  aB = fma2(zq[7].y, wD.y, aB);
        ulonglong2 st; st.x = aA; st.y = aB;
        *reinterpret_cast<ulonglong2*>(&obase[(size_t)o * TT]) = st;
    }
}

// ---------------------------------------------------------------------------
extern "C" void kernel_launch(void* const* d_in, const int* in_sizes, int n_in,
                              void* d_out, int out_size) {
    const float* z     = (const float*)d_in[0];
    const float* w_in  = (const float*)d_in[1];
    const float* b_in  = (const float*)d_in[2];
    const float* w_out = (const float*)d_in[3];
    const float* b_out = (const float*)d_in[4];
    const float* cb    = (const float*)d_in[5];
    float* out = (float*)d_out;

    dim3 g1(TT / 16, BB);              // (128, 8) = 1024 CTAs, prep folded in
    k_inproj<<<g1, 256>>>(z, w_in, b_in, cb, w_out, b_out, out);

    dim3 g3(NTOK / TOKBLK, NSPLIT);    // (16, 37) = 592 CTAs = one full wave
    k_search<<<g3, 256>>>();

    k_zq<<<NTOK / 2 / 32, 256>>>(cb, out);   // 256 CTAs, (pair, k) work-items

    dim3 g5(TT / 1024, BB, DIN / 16);  // (2, 8, 64) = 1024 CTAs
    k_outproj<<<g5, 256>>>(out);
}